// round 1
// baseline (speedup 1.0000x reference)
#include <cuda_runtime.h>
#include <math.h>

#define VSZ 128
#define HW  (VSZ*VSZ)          // 16384
#define NB  4
#define NP  32
#define PE  16
#define SHARP 100.0f
#define EPSF  1e-8f

// ---------------- scratch (static device globals; no allocation) ------------
// per edge: a = {v0x, v0y, v1y, ex}; c = {ey, inv_norm, ex/(ey+eps), 0}
__device__ float4 g_edges[NB*NP*PE*2];      // 64 KB
__device__ float  g_active[NB*NP];
__device__ int    g_hv[NB];
__device__ float  g_combined[NB*HW];        // 256 KB

// ---------------- kernel A: per-polygon setup -------------------------------
__global__ void setup_kernel(const float* __restrict__ polygons,
                             const float* __restrict__ attributes,
                             const float* __restrict__ validity)
{
    int t = threadIdx.x;
    if (t >= NB*NP) return;
    int b = t / NP;
    int n = t % NP;

    const float* poly = polygons + (size_t)t * PE * 2;

    // vertex compaction: valid verts (x+y != 0) first, stable order
    float vx[PE], vy[PE];
    int K = 0;
    #pragma unroll
    for (int i = 0; i < PE; i++) {
        float x = poly[2*i + 0];
        float y = poly[2*i + 1];
        if (x + y != 0.0f) { vx[K] = x; vy[K] = y; K++; }
    }

    for (int e = 0; e < PE; e++) {
        float4 a, c;
        if (e < K) {
            int j = (e == K-1) ? 0 : e+1;
            float x0 = vx[e], y0 = vy[e];
            float x1 = vx[j], y1 = vy[j];
            float ex = x1 - x0, ey = y1 - y0;
            float inv  = 1.0f / (ex*ex + ey*ey + EPSF);
            float iey  = 1.0f / (ey + EPSF);
            a = make_float4(x0, y0, y1, ex);
            c = make_float4(ey, inv, ex * iey, 0.0f);
        } else {
            // sentinel: huge distance, never crosses
            a = make_float4(0.0f, 1e30f, 1e30f, 0.0f);
            c = make_float4(0.0f, 0.0f, 0.0f, 0.0f);
        }
        g_edges[(t*PE + e)*2 + 0] = a;
        g_edges[(t*PE + e)*2 + 1] = c;
    }

    g_active[t] = (K >= 3 && validity[t] >= 0.5f) ? 1.0f : 0.0f;

    if (n == 0) {
        float av = attributes[b];                  // shape (B,1)
        av = fminf(fmaxf(av, 0.0f), 1.0f);
        int hv = (int)rintf(av * (float)VSZ);      // round-half-even like jnp.rint
        hv = min(max(hv, 1), VSZ);
        g_hv[b] = hv;
    }
}

// ---------------- kernel B: per-pixel SDF + soft mask + max over polys ------
__global__ void __launch_bounds__(256) sdf_kernel()
{
    __shared__ float4 sh[NP*PE*2];   // 1024 float4 = 16 KB
    __shared__ float  sact[NP];

    int b    = blockIdx.x >> 6;      // 64 tiles per batch
    int tile = blockIdx.x & 63;
    int t    = threadIdx.x;

    const float4* ge = g_edges + (size_t)b * NP * PE * 2;
    #pragma unroll
    for (int i = 0; i < 4; i++)
        sh[t + 256*i] = ge[t + 256*i];
    if (t < NP) sact[t] = g_active[b*NP + t];
    __syncthreads();

    int m = tile * 256 + t;
    float px = (float)(m & (VSZ-1)) * (1.0f/(float)(VSZ-1));
    float py = (float)(m >> 7)      * (1.0f/(float)(VSZ-1));

    float comb = 0.0f;
    for (int n = 0; n < NP; n++) {
        if (sact[n] == 0.0f) continue;   // uniform across block: no divergence
        const float4* E = sh + n*PE*2;
        float mind2 = 3.4e38f;
        int cnt = 0;
        #pragma unroll
        for (int e = 0; e < PE; e++) {
            float4 a = E[2*e + 0];
            float4 c = E[2*e + 1];
            float vx = px - a.x;
            float vy = py - a.y;
            float tt = (vx*a.w + vy*c.x) * c.y;
            tt = fminf(fmaxf(tt, 0.0f), 1.0f);
            float dx = fmaf(-tt, a.w, vx);
            float dy = fmaf(-tt, c.x, vy);
            float d2 = fmaf(dx, dx, dy*dy);
            mind2 = fminf(mind2, d2);
            // crossing test (exact comparison semantics of the reference)
            bool yc = ((a.y <= py) && (a.z > py)) || ((a.z <= py) && (a.y > py));
            float ix = fmaf(c.z, vy, a.x);
            cnt ^= (yc && (ix > px)) ? 1 : 0;
        }
        float d   = sqrtf(mind2);
        float sdf = cnt ? -d : d;
        float mv  = 1.0f / (1.0f + expf(SHARP * sdf));
        comb = fmaxf(comb, mv);
    }
    g_combined[b*HW + m] = comb;
}

// ---------------- kernel C: depth broadcast (float4 stores) -----------------
__global__ void __launch_bounds__(256) bcast_kernel(float4* __restrict__ out)
{
    int q = blockIdx.x * 256 + threadIdx.x;     // 0 .. 2097151 (float4 units)
    int b   = q >> 19;                          // D*HW/4 = 524288 per batch
    int rem = q & ((1 << 19) - 1);
    int d   = rem >> 12;                        // HW/4 = 4096 per depth slice
    int m4  = rem & 4095;

    float4 val = make_float4(0.0f, 0.0f, 0.0f, 0.0f);
    if (d < g_hv[b])
        val = reinterpret_cast<const float4*>(g_combined)[b*4096 + m4];
    out[q] = val;
}

// ---------------- launch ----------------------------------------------------
extern "C" void kernel_launch(void* const* d_in, const int* in_sizes, int n_in,
                              void* d_out, int out_size)
{
    const float* polygons   = (const float*)d_in[0];   // (4,32,16,2)
    const float* attributes = (const float*)d_in[1];   // (4,1)
    const float* validity   = (const float*)d_in[2];   // (4,32)
    float* out = (float*)d_out;                        // (4,128,128,128)

    setup_kernel<<<1, 128>>>(polygons, attributes, validity);
    sdf_kernel<<<NB*64, 256>>>();
    bcast_kernel<<<(NB*VSZ*HW/4 + 255)/256, 256>>>((float4*)out);
}

// round 2
// speedup vs baseline: 1.7051x; 1.7051x over previous
#include <cuda_runtime.h>
#include <math.h>

#define VSZ 128
#define HW  (VSZ*VSZ)          // 16384
#define NB  4
#define NP  32
#define PE  16
#define EPSF  1e-8f

// ---------------- scratch (static device globals; no allocation) ------------
// per edge: A = {v0x, v0y, v1y, ex}; Bv = {ey, ex*inv, ey*inv, ex/(ey+eps)}
__device__ float4 g_edges[NB*NP*PE*2];      // 64 KB
__device__ float  g_active[NB*NP];
__device__ int    g_hv[NB];

// ---------------- kernel A: warp-per-polygon setup --------------------------
__global__ __launch_bounds__(256) void setup_kernel(
    const float* __restrict__ polygons,
    const float* __restrict__ attributes,
    const float* __restrict__ validity)
{
    __shared__ float2 shv[8][16];
    int w = threadIdx.x >> 5;
    int l = threadIdx.x & 31;
    int poly = blockIdx.x * 8 + w;            // 0..127

    const float* pp = polygons + (size_t)poly * PE * 2;
    float x = 0.0f, y = 0.0f;
    bool valid = false;
    if (l < PE) {
        x = pp[2*l + 0];
        y = pp[2*l + 1];
        valid = (x + y) != 0.0f;
    }
    unsigned mask = __ballot_sync(0xffffffffu, valid);
    int K   = __popc(mask);
    int pos = __popc(mask & ((1u << l) - 1u));
    if (valid) shv[w][pos] = make_float2(x, y);
    __syncwarp();

    if (l < PE) {
        float4 A, Bv;
        if (l < K) {
            float2 v0 = shv[w][l];
            float2 v1 = shv[w][(l + 1 == K) ? 0 : l + 1];
            float ex = v1.x - v0.x;
            float ey = v1.y - v0.y;
            float inv = 1.0f / (ex*ex + ey*ey + EPSF);
            A  = make_float4(v0.x, v0.y, v1.y, ex);
            Bv = make_float4(ey, ex*inv, ey*inv, ex / (ey + EPSF));
        } else {
            // sentinel: never crosses (yc=false), huge distance (d2 -> inf)
            A  = make_float4(0.0f, 1e30f, 1e30f, 0.0f);
            Bv = make_float4(0.0f, 0.0f, 0.0f, 0.0f);
        }
        g_edges[(poly*PE + l)*2 + 0] = A;
        g_edges[(poly*PE + l)*2 + 1] = Bv;
    }
    if (l == 0)
        g_active[poly] = (K >= 3 && validity[poly] >= 0.5f) ? 1.0f : 0.0f;

    if (blockIdx.x == 0 && threadIdx.x < NB) {
        float av = attributes[threadIdx.x];            // (B,1)
        av = fminf(fmaxf(av, 0.0f), 1.0f);
        int hv = (int)rintf(av * (float)VSZ);          // round-half-even like jnp.rint
        hv = min(max(hv, 1), VSZ);
        g_hv[threadIdx.x] = hv;
    }
}

// ------- kernel B: fused SDF + soft mask (via min-sdf) + depth broadcast ----
// 128 blocks (one wave), 256 threads, 2 pixels per thread (same row).
__global__ __launch_bounds__(256) void fused_kernel(float* __restrict__ out)
{
    __shared__ float4 sh[NP*PE*2];   // 16 KB
    __shared__ float  sact[NP];
    __shared__ int    s_hv;

    int b    = blockIdx.x >> 5;      // 32 tiles per batch
    int tile = blockIdx.x & 31;
    int t    = threadIdx.x;

    const float4* ge = g_edges + (size_t)b * NP * PE * 2;
    #pragma unroll
    for (int i = 0; i < 4; i++)
        sh[t + 256*i] = ge[t + 256*i];
    if (t < NP) sact[t] = g_active[b*NP + t];
    if (t == 0) s_hv = g_hv[b];
    __syncthreads();

    int m0 = tile * 512 + t * 2;     // two adjacent pixels in a row
    const float h = 1.0f / (float)(VSZ - 1);
    float px0 = (float)(m0 & (VSZ-1)) * h;
    float px1 = px0 + h;
    float py  = (float)(m0 >> 7) * h;

    // running best signed distance as (inside, d2): inside beats outside;
    // among inside larger d2 wins (more negative sdf); among outside smaller d2.
    float bD2a = 3.4e38f, bD2b = 3.4e38f;
    bool  bIa  = false,   bIb  = false;

    for (int n = 0; n < NP; n++) {
        if (sact[n] == 0.0f) continue;         // block-uniform: no divergence
        const float4* E = sh + n * (PE*2);
        float m2a = 3.4e38f, m2b = 3.4e38f;
        bool  ca = false, cb = false;
        #pragma unroll
        for (int e = 0; e < PE; e++) {
            float4 A  = E[2*e + 0];
            float4 Bv = E[2*e + 1];
            // shared per (edge,row)
            float vy    = py - A.y;
            bool  yc    = (A.y <= py) != (A.z <= py);   // exact xor form of ref test
            float ix    = fmaf(Bv.w, vy, A.x);
            float vyeyi = vy * Bv.z;
            float vx0   = px0 - A.x;
            float vx1   = vx0 + h;
            // per-pixel
            float t0 = fmaf(vx0, Bv.y, vyeyi);
            float t1 = fmaf(vx1, Bv.y, vyeyi);
            t0 = fminf(fmaxf(t0, 0.0f), 1.0f);
            t1 = fminf(fmaxf(t1, 0.0f), 1.0f);
            float dx0 = fmaf(-t0, A.w, vx0);
            float dy0 = fmaf(-t0, Bv.x, vy);
            float dx1 = fmaf(-t1, A.w, vx1);
            float dy1 = fmaf(-t1, Bv.x, vy);
            float d20 = fmaf(dy0, dy0, dx0*dx0);
            float d21 = fmaf(dy1, dy1, dx1*dx1);
            m2a = fminf(m2a, d20);
            m2b = fminf(m2b, d21);
            ca ^= (yc && (ix > px0));
            cb ^= (yc && (ix > px1));
        }
        bool ta = (ca != bIa) ? ca : (ca ? (m2a > bD2a) : (m2a < bD2a));
        if (ta) { bIa = ca; bD2a = m2a; }
        bool tb = (cb != bIb) ? cb : (cb ? (m2b > bD2b) : (m2b < bD2b));
        if (tb) { bIb = cb; bD2b = m2b; }
    }

    // sigmoid(-100*sdf) of the min signed sdf == max of per-poly masks
    float da = sqrtf(bD2a);
    float db = sqrtf(bD2b);
    float sa = bIa ? -da : da;
    float sb = bIb ? -db : db;
    float va = __fdividef(1.0f, 1.0f + __expf(100.0f * sa));
    float vb = __fdividef(1.0f, 1.0f + __expf(100.0f * sb));

    float2 cv = make_float2(va, vb);
    float2 zv = make_float2(0.0f, 0.0f);
    char* basep = (char*)out + ((size_t)b * VSZ * HW + (size_t)m0) * sizeof(float);
    int hv = s_hv;
    int d = 0;
    #pragma unroll 4
    for (; d < hv; d++)
        *(float2*)(basep + (size_t)d * HW * sizeof(float)) = cv;
    #pragma unroll 4
    for (; d < VSZ; d++)
        *(float2*)(basep + (size_t)d * HW * sizeof(float)) = zv;
}

// ---------------- launch ----------------------------------------------------
extern "C" void kernel_launch(void* const* d_in, const int* in_sizes, int n_in,
                              void* d_out, int out_size)
{
    const float* polygons   = (const float*)d_in[0];   // (4,32,16,2)
    const float* attributes = (const float*)d_in[1];   // (4,1)
    const float* validity   = (const float*)d_in[2];   // (4,32)
    float* out = (float*)d_out;                        // (4,128,128,128)

    setup_kernel<<<16, 256>>>(polygons, attributes, validity);
    fused_kernel<<<NB*32, 256>>>(out);
}